// round 7
// baseline (speedup 1.0000x reference)
#include <cuda_runtime.h>
#include <cuda_fp16.h>
#include <math.h>
#include <stdint.h>

// -------------------- problem constants --------------------
#define M_N     8192
#define IN_DIM  3000
#define K_PAD   3008        // 47 * 64
#define HID     512
#define LAT     30
#define MAXD    192

#define BM      128
#define BN      256
#define BK      64
#define NCHUNK  (K_PAD / BK)   // 47
#define NSTAGE  4

// SMEM stage layout (bytes): Ah[128x64]=16K, Bh[256x64]=32K
#define A_BYTES   16384
#define B_BYTES   32768
#define STAGE     (A_BYTES + B_BYTES)            // 49152
#define SMEM_TOTAL (NSTAGE * STAGE)              // 196608

// -------------------- static device scratch --------------------
__device__ __align__(16) __half g_Ah[(size_t)M_N * K_PAD];    // 49 MB fp16 A
__device__ __align__(16) __half g_Xh[(size_t)M_N * HID];      // 8 MB fp16 X
__device__ float g_f0[M_N];
__device__ float g_f1[M_N];
__device__ int   g_idx[M_N * MAXD];
__device__ int   g_cnt[M_N];
__device__ __align__(16) __half g_Bhi[(size_t)HID * K_PAD];   // [n][k] fp16

// -------------------- PTX helpers --------------------
__device__ __forceinline__ uint32_t smem_u32(const void* p) {
    uint32_t a;
    asm("{ .reg .u64 t; cvta.to.shared.u64 t, %1; cvt.u32.u64 %0, t; }"
        : "=r"(a) : "l"(p));
    return a;
}

__device__ __forceinline__ uint32_t sw128(uint32_t off) {
    return off ^ ((off >> 3) & 0x70);
}

__device__ __forceinline__ void cp_async16(uint32_t dst, const void* src) {
    asm volatile("cp.async.cg.shared.global [%0], [%1], 16;"
                 :: "r"(dst), "l"(src));
}
__device__ __forceinline__ void cp_commit() {
    asm volatile("cp.async.commit_group;" ::: "memory");
}

__device__ __forceinline__ void ldmx4(uint32_t* r, uint32_t addr) {
    asm volatile("ldmatrix.sync.aligned.m8n8.x4.shared.b16 {%0,%1,%2,%3}, [%4];"
                 : "=r"(r[0]), "=r"(r[1]), "=r"(r[2]), "=r"(r[3]) : "r"(addr));
}

__device__ __forceinline__ void mma_fp16(float* d, const uint32_t* a,
                                         const uint32_t* b) {
    asm volatile(
        "mma.sync.aligned.m16n8k16.row.col.f32.f16.f16.f32 "
        "{%0,%1,%2,%3}, {%4,%5,%6,%7}, {%8,%9}, {%0,%1,%2,%3};"
        : "+f"(d[0]), "+f"(d[1]), "+f"(d[2]), "+f"(d[3])
        : "r"(a[0]), "r"(a[1]), "r"(a[2]), "r"(a[3]), "r"(b[0]), "r"(b[1]));
}

// -------------------- Kernel 0a: A fp32 -> fp16 (padded K) ------------------
__global__ __launch_bounds__(256)
void convA_kernel(const float* __restrict__ A, __half* __restrict__ Ah)
{
    const int row = blockIdx.y;
    const int q   = blockIdx.x * 256 + threadIdx.x;   // float4 index within row
    if (q >= K_PAD / 4) return;                        // 752 groups
    __half2 h0, h1;
    if (q < IN_DIM / 4) {                              // 750 full groups
        float4 a = *(const float4*)(A + (size_t)row * IN_DIM + q * 4);
        h0 = __floats2half2_rn(a.x, a.y);
        h1 = __floats2half2_rn(a.z, a.w);
    } else {                                           // pad 3000..3007
        h0 = __floats2half2_rn(0.f, 0.f);
        h1 = h0;
    }
    *(uint2*)(Ah + (size_t)row * K_PAD + q * 4) =
        make_uint2(*(const uint32_t*)&h0, *(const uint32_t*)&h1);
}

// -------------------- Kernel 0b: transpose W0 -> [n][k] fp16 ----------------
__global__ void convB_kernel(const float* __restrict__ W,
                             __half* __restrict__ hi)
{
    __shared__ float tile[32][33];
    int k0 = blockIdx.x * 32;
    int n0 = blockIdx.y * 32;
    int tx = threadIdx.x, ty = threadIdx.y;   // block (32, 8)
#pragma unroll
    for (int r = 0; r < 4; r++) {
        int kk = ty + r * 8;
        int k  = k0 + kk;
        tile[kk][tx] = (k < IN_DIM) ? W[(size_t)k * HID + n0 + tx] : 0.0f;
    }
    __syncthreads();
#pragma unroll
    for (int r = 0; r < 4; r++) {
        int nn = ty + r * 8;
        hi[(size_t)(n0 + nn) * K_PAD + k0 + tx] = __float2half(tile[tx][nn]);
    }
}

// -------------------- Kernel 1: fp16 warp-MMA GEMM, pure cp.async -----------
// Xh[8192,512] = fp16( Ah[8192,3008] @ Bt^T ), fp32 accum inside.

__device__ __forceinline__ void ldg_chunk(uint32_t base, int k0, int t,
                                          const __half* Ah, const __half* Bh)
{
    // A tile: 128 rows x 8 segs of 16B = 1024 cp.async; 512 threads -> 2 each
#pragma unroll
    for (int i = 0; i < 2; i++) {
        int lin = t + i * 512;
        int row = lin >> 3, seg = lin & 7;
        uint32_t so = sw128((uint32_t)(row * 128 + seg * 16));
        cp_async16(base + so, Ah + (size_t)row * K_PAD + k0 + seg * 8);
    }
    // B tile: 256 rows x 8 segs = 2048 -> 4 each
#pragma unroll
    for (int i = 0; i < 4; i++) {
        int lin = t + i * 512;
        int row = lin >> 3, seg = lin & 7;
        uint32_t so = sw128((uint32_t)(row * 128 + seg * 16));
        cp_async16(base + A_BYTES + so, Bh + (size_t)row * K_PAD + k0 + seg * 8);
    }
}

__global__ __launch_bounds__(512, 1)
void gemm_mma_kernel(__half* __restrict__ Xout)
{
    extern __shared__ __align__(1024) char smem[];
    const uint32_t sb = smem_u32(smem);
    const int t    = threadIdx.x;
    const int wid  = t >> 5;
    const int lane = t & 31;
    const int wy   = wid >> 2;   // 0..3 : m group (32 rows)
    const int wx   = wid & 3;    // 0..3 : n group (64 cols)

    const __half* Ah = g_Ah  + (size_t)(blockIdx.y * BM) * K_PAD;
    const __half* Bh = g_Bhi + (size_t)(blockIdx.x * BN) * K_PAD;

    float acc[2][8][4];
#pragma unroll
    for (int i = 0; i < 2; i++)
#pragma unroll
        for (int j = 0; j < 8; j++)
#pragma unroll
            for (int q = 0; q < 4; q++) acc[i][j][q] = 0.0f;

    const int a_row = (lane & 15);
    const int a_k8  = (lane >> 4);
    const int b_row = ((lane >> 4) << 3) + (lane & 7);
    const int b_k8  = (lane >> 3) & 1;

    // prologue: stages 0..2
#pragma unroll
    for (int s = 0; s < NSTAGE - 1; s++) {
        ldg_chunk(sb + s * STAGE, s * BK, t, Ah, Bh);
        cp_commit();
    }

    for (int c = 0; c < NCHUNK; c++) {
        asm volatile("cp.async.wait_group %0;" :: "n"(NSTAGE - 2) : "memory");
        __syncthreads();

        // prefetch c+3 into the stage freed last iteration
        if (c + NSTAGE - 1 < NCHUNK)
            ldg_chunk(sb + ((c + NSTAGE - 1) % NSTAGE) * STAGE,
                      (c + NSTAGE - 1) * BK, t, Ah, Bh);
        cp_commit();

        const uint32_t base = sb + (c % NSTAGE) * STAGE;
        const uint32_t aH = base;
        const uint32_t bH = base + A_BYTES;

#pragma unroll
        for (int kk = 0; kk < 4; kk++) {
            uint32_t ah[2][4];
#pragma unroll
            for (int mt = 0; mt < 2; mt++) {
                int row = wy * 32 + mt * 16 + a_row;
                int kcol = kk * 16 + a_k8 * 8;
                uint32_t off = sw128((uint32_t)(row * 128 + kcol * 2));
                ldmx4(ah[mt], aH + off);
            }
#pragma unroll
            for (int ng = 0; ng < 4; ng++) {
                int n = wx * 64 + ng * 16 + b_row;
                int kcol = kk * 16 + b_k8 * 8;
                uint32_t off = sw128((uint32_t)(n * 128 + kcol * 2));
                uint32_t bh[4];
                ldmx4(bh, bH + off);
#pragma unroll
                for (int mt = 0; mt < 2; mt++) {
                    mma_fp16(acc[mt][2 * ng],     ah[mt], bh);
                    mma_fp16(acc[mt][2 * ng + 1], ah[mt], bh + 2);
                }
            }
        }
        __syncthreads();
    }

    // epilogue: write fp16 X
    __half* dst = Xout + (size_t)(blockIdx.y * BM + wy * 32) * HID
                + blockIdx.x * BN + wx * 64;
    const int r0 = lane >> 2;
    const int c0 = (lane & 3) * 2;
#pragma unroll
    for (int mt = 0; mt < 2; mt++) {
#pragma unroll
        for (int nt = 0; nt < 8; nt++) {
            __half2 h01 = __floats2half2_rn(acc[mt][nt][0], acc[mt][nt][1]);
            __half2 h23 = __floats2half2_rn(acc[mt][nt][2], acc[mt][nt][3]);
            *(__half2*)(dst + (size_t)(mt * 16 + r0) * HID + nt * 8 + c0) = h01;
            *(__half2*)(dst + (size_t)(mt * 16 + r0 + 8) * HID + nt * 8 + c0) = h23;
        }
    }
}

// -------------------- Kernel 2: f0 = X@v0, f1 = X@v1 (fp16 X) ---------------
__global__ void fvec_kernel(const __half* __restrict__ Xh,
                            const float* __restrict__ v0,
                            const float* __restrict__ v1,
                            float* __restrict__ f0, float* __restrict__ f1)
{
    int row  = blockIdx.x * 8 + (threadIdx.x >> 5);
    int lane = threadIdx.x & 31;
    const uint4* xr = (const uint4*)(Xh + (size_t)row * HID);  // 64 uint4/row
    const float4* w0 = (const float4*)v0;
    const float4* w1 = (const float4*)v1;
    float s0 = 0.f, s1 = 0.f;
#pragma unroll
    for (int i = 0; i < 2; i++) {
        int u = lane + i * 32;            // uint4 index: 8 halves
        uint4 xv = xr[u];
        const __half2* xp = (const __half2*)&xv;
#pragma unroll
        for (int p = 0; p < 2; p++) {     // two float4 groups of 4
            float2 e0 = __half22float2(xp[p * 2 + 0]);
            float2 e1 = __half22float2(xp[p * 2 + 1]);
            float4 a = w0[u * 2 + p];
            float4 b = w1[u * 2 + p];
            s0 += e0.x * a.x + e0.y * a.y + e1.x * a.z + e1.y * a.w;
            s1 += e0.x * b.x + e0.y * b.y + e1.x * b.z + e1.y * b.w;
        }
    }
#pragma unroll
    for (int o = 16; o > 0; o >>= 1) {
        s0 += __shfl_xor_sync(0xffffffffu, s0, o);
        s1 += __shfl_xor_sync(0xffffffffu, s1, o);
    }
    if (lane == 0) { f0[row] = s0; f1[row] = s1; }
}

// -------------------- Kernel 3: sparsify graph rows -------------------------
__global__ __launch_bounds__(512)
void sparsify_kernel(const float* __restrict__ graph,
                     int* __restrict__ idx, int* __restrict__ cnt)
{
    int row = blockIdx.x;
    __shared__ int c;
    if (threadIdx.x == 0) c = 0;
    __syncthreads();
    const float4* g = (const float4*)(graph + (size_t)row * M_N);
    const int t = threadIdx.x;
    float4 v[4];
#pragma unroll
    for (int i = 0; i < 4; i++) v[i] = __ldg(&g[t + i * 512]);
#pragma unroll
    for (int i = 0; i < 4; i++) {
        int b = (t + i * 512) * 4;
        if (v[i].x != 0.0f) { int s = atomicAdd(&c, 1); if (s < MAXD) idx[row * MAXD + s] = b + 0; }
        if (v[i].y != 0.0f) { int s = atomicAdd(&c, 1); if (s < MAXD) idx[row * MAXD + s] = b + 1; }
        if (v[i].z != 0.0f) { int s = atomicAdd(&c, 1); if (s < MAXD) idx[row * MAXD + s] = b + 2; }
        if (v[i].w != 0.0f) { int s = atomicAdd(&c, 1); if (s < MAXD) idx[row * MAXD + s] = b + 3; }
    }
    __syncthreads();
    if (threadIdx.x == 0) cnt[row] = (c < MAXD) ? c : MAXD;
}

// -------------------- Kernel 4: fused attention + agg + ELU + W1 ------------
__global__ __launch_bounds__(256)
void attn_kernel(const __half* __restrict__ Xh,
                 const float* __restrict__ f0, const float* __restrict__ f1,
                 const float* __restrict__ W1,
                 const int* __restrict__ idx, const int* __restrict__ cnt,
                 float* __restrict__ out)
{
    const int row = blockIdx.x;
    const int t   = threadIdx.x;

    __shared__ int   s_idx[MAXD];
    __shared__ float s_alpha[MAXD];
    __shared__ float red[256];
    __shared__ float s_hq[4 * HID];
    __shared__ float s_h[HID];
    __shared__ float s_part[8][32];

    const int n = cnt[row];              // >= 1 (self loop)
    for (int j = t; j < n; j += 256) s_idx[j] = idx[row * MAXD + j];
    __syncthreads();

    const float f0i = f0[row];

    float my = 0.0f, mx = -INFINITY;
    if (t < n) {
        float e   = f0i + f1[s_idx[t]];
        float sig = 1.0f / (1.0f + expf(-e));
        my = sig - 0.5f;
        mx = my;
    }
    red[t] = mx;
    __syncthreads();
#pragma unroll
    for (int o = 128; o > 0; o >>= 1) {
        if (t < o) red[t] = fmaxf(red[t], red[t + o]);
        __syncthreads();
    }
    const float m = red[0];
    __syncthreads();

    float e = 0.0f;
    if (t < n) e = expf(my - m);
    red[t] = e;
    __syncthreads();
#pragma unroll
    for (int o = 128; o > 0; o >>= 1) {
        if (t < o) red[t] += red[t + o];
        __syncthreads();
    }
    const float ssum = fmaxf(red[0], 1e-30f);
    if (t < n) s_alpha[t] = e / ssum;
    __syncthreads();

    // aggregation: quarter q handles neighbors j ≡ q (mod 4);
    // each thread owns 8 output cols = one uint4 (8 halves) per neighbor
    const int q = t >> 6;
    const int u = t & 63;
    float acc[8];
#pragma unroll
    for (int i = 0; i < 8; i++) acc[i] = 0.0f;
    for (int j = q; j < n; j += 4) {
        const float a = s_alpha[j];
        const uint4 xv = *((const uint4*)(Xh + (size_t)s_idx[j] * HID) + u);
        const __half2* xp = (const __half2*)&xv;
#pragma unroll
        for (int p = 0; p < 4; p++) {
            float2 f = __half22float2(xp[p]);
            acc[2 * p]     += a * f.x;
            acc[2 * p + 1] += a * f.y;
        }
    }
    ((float4*)(s_hq + q * HID))[u * 2]     =
        make_float4(acc[0], acc[1], acc[2], acc[3]);
    ((float4*)(s_hq + q * HID))[u * 2 + 1] =
        make_float4(acc[4], acc[5], acc[6], acc[7]);
    __syncthreads();

    if (t < 128) {
        float4 r = make_float4(0.f, 0.f, 0.f, 0.f);
#pragma unroll
        for (int qq = 0; qq < 4; qq++) {
            float4 v = ((const float4*)s_hq)[qq * 128 + t];
            r.x += v.x; r.y += v.y; r.z += v.z; r.w += v.w;
        }
        r.x = (r.x > 0.f) ? r.x : expm1f(r.x);
        r.y = (r.y > 0.f) ? r.y : expm1f(r.y);
        r.z = (r.z > 0.f) ? r.z : expm1f(r.z);
        r.w = (r.w > 0.f) ? r.w : expm1f(r.w);
        ((float4*)s_h)[t] = r;
    }
    __syncthreads();

    if (t < 240) {
        int k  = t % 30;
        int sl = t / 30;
        float p = 0.0f;
        const int d0 = sl * 64;
#pragma unroll 8
        for (int d = d0; d < d0 + 64; d++) p += s_h[d] * W1[d * LAT + k];
        s_part[sl][k] = p;
    }
    __syncthreads();
    if (t < LAT) {
        float r = 0.0f;
#pragma unroll
        for (int sl = 0; sl < 8; sl++) r += s_part[sl][t];
        out[(size_t)row * LAT + t] = r;
    }
}

// -------------------- launch -------------------------------------------------
extern "C" void kernel_launch(void* const* d_in, const int* in_sizes, int n_in,
                              void* d_out, int out_size)
{
    const float* node_features = (const float*)d_in[0]; // [8192,3000]
    const float* graph         = (const float*)d_in[1]; // [8192,8192]
    const float* W0            = (const float*)d_in[2]; // [3000,512]
    const float* v0            = (const float*)d_in[3]; // [512]
    const float* v1            = (const float*)d_in[4]; // [512]
    const float* W1            = (const float*)d_in[5]; // [512,30]
    float* out = (float*)d_out;

    __half *Ah, *Xh, *Bhi;
    float *f0, *f1;
    int *idx, *cnt;
    cudaGetSymbolAddress((void**)&Ah,  g_Ah);
    cudaGetSymbolAddress((void**)&Xh,  g_Xh);
    cudaGetSymbolAddress((void**)&f0,  g_f0);
    cudaGetSymbolAddress((void**)&f1,  g_f1);
    cudaGetSymbolAddress((void**)&idx, g_idx);
    cudaGetSymbolAddress((void**)&cnt, g_cnt);
    cudaGetSymbolAddress((void**)&Bhi, g_Bhi);

    // one-time resources (created on the uncaptured correctness call)
    static cudaStream_t s2 = nullptr;
    static cudaEvent_t evFork = nullptr, evJoin = nullptr;
    if (s2 == nullptr) {
        cudaStreamCreateWithFlags(&s2, cudaStreamNonBlocking);
        cudaEventCreateWithFlags(&evFork, cudaEventDisableTiming);
        cudaEventCreateWithFlags(&evJoin, cudaEventDisableTiming);
        cudaFuncSetAttribute(gemm_mma_kernel,
                             cudaFuncAttributeMaxDynamicSharedMemorySize,
                             SMEM_TOTAL);
    }

    // fork: sparsify runs on s2 concurrently with the GEMM chain
    cudaEventRecord(evFork, 0);
    cudaStreamWaitEvent(s2, evFork, 0);
    sparsify_kernel<<<M_N, 512, 0, s2>>>(graph, idx, cnt);
    cudaEventRecord(evJoin, s2);

    // main chain on the default stream
    convA_kernel<<<dim3(3, M_N), 256>>>(node_features, Ah);
    convB_kernel<<<dim3(K_PAD / 32, HID / 32), dim3(32, 8)>>>(W0, Bhi);
    gemm_mma_kernel<<<dim3(HID / BN, M_N / BM), 512, SMEM_TOTAL>>>(Xh);
    fvec_kernel<<<M_N / 8, 256>>>(Xh, v0, v1, f0, f1);

    // join: attn needs both the GEMM chain and sparsify
    cudaStreamWaitEvent(0, evJoin, 0);
    attn_kernel<<<M_N, 256>>>(Xh, f0, f1, W1, idx, cnt, out);
}

// round 9
// speedup vs baseline: 1.1077x; 1.1077x over previous
#include <cuda_runtime.h>
#include <cuda_fp16.h>
#include <math.h>
#include <stdint.h>

// -------------------- problem constants --------------------
#define M_N     8192
#define IN_DIM  3000
#define K_PAD   3008        // 47 * 64
#define HID     512
#define LAT     30
#define MAXD    192

#define BM      128
#define BN      256
#define BK      64
#define NCHUNK  (K_PAD / BK)   // 47
#define NSTAGE  4

// SMEM stage layout (bytes): Ah[128x64]=16K, Bh[256x64]=32K
#define A_BYTES   16384
#define B_BYTES   32768
#define STAGE     (A_BYTES + B_BYTES)            // 49152
#define SMEM_TOTAL (NSTAGE * STAGE)              // 196608

// -------------------- static device scratch --------------------
__device__ __align__(16) __half g_Ah[(size_t)M_N * K_PAD];    // 49 MB fp16 A
__device__ __align__(16) __half g_Xh[(size_t)M_N * HID];      // 8 MB fp16 X
__device__ float g_f0[M_N];
__device__ float g_f1[M_N];
__device__ int   g_idx[M_N * MAXD];
__device__ int   g_cnt[M_N];
__device__ __align__(16) __half g_Bhi[(size_t)HID * K_PAD];   // [n][k] fp16

// -------------------- PTX helpers --------------------
__device__ __forceinline__ uint32_t smem_u32(const void* p) {
    uint32_t a;
    asm("{ .reg .u64 t; cvta.to.shared.u64 t, %1; cvt.u32.u64 %0, t; }"
        : "=r"(a) : "l"(p));
    return a;
}

__device__ __forceinline__ uint32_t sw128(uint32_t off) {
    return off ^ ((off >> 3) & 0x70);
}

__device__ __forceinline__ void cp_async16(uint32_t dst, const void* src) {
    asm volatile("cp.async.cg.shared.global [%0], [%1], 16;"
                 :: "r"(dst), "l"(src));
}
__device__ __forceinline__ void cp_commit() {
    asm volatile("cp.async.commit_group;" ::: "memory");
}

__device__ __forceinline__ void ldmx4(uint32_t* r, uint32_t addr) {
    asm volatile("ldmatrix.sync.aligned.m8n8.x4.shared.b16 {%0,%1,%2,%3}, [%4];"
                 : "=r"(r[0]), "=r"(r[1]), "=r"(r[2]), "=r"(r[3]) : "r"(addr));
}

__device__ __forceinline__ void mma_fp16(float* d, const uint32_t* a,
                                         const uint32_t* b) {
    asm volatile(
        "mma.sync.aligned.m16n8k16.row.col.f32.f16.f16.f32 "
        "{%0,%1,%2,%3}, {%4,%5,%6,%7}, {%8,%9}, {%0,%1,%2,%3};"
        : "+f"(d[0]), "+f"(d[1]), "+f"(d[2]), "+f"(d[3])
        : "r"(a[0]), "r"(a[1]), "r"(a[2]), "r"(a[3]), "r"(b[0]), "r"(b[1]));
}

// -------------------- Kernel 0a: A fp32 -> fp16 (padded K) ------------------
__global__ __launch_bounds__(256)
void convA_kernel(const float* __restrict__ A, __half* __restrict__ Ah)
{
    const int row = blockIdx.y;
    const int q   = blockIdx.x * 256 + threadIdx.x;   // float4 index within row
    if (q >= K_PAD / 4) return;                        // 752 groups
    __half2 h0, h1;
    if (q < IN_DIM / 4) {                              // 750 full groups
        float4 a = *(const float4*)(A + (size_t)row * IN_DIM + q * 4);
        h0 = __floats2half2_rn(a.x, a.y);
        h1 = __floats2half2_rn(a.z, a.w);
    } else {                                           // pad 3000..3007
        h0 = __floats2half2_rn(0.f, 0.f);
        h1 = h0;
    }
    *(uint2*)(Ah + (size_t)row * K_PAD + q * 4) =
        make_uint2(*(const uint32_t*)&h0, *(const uint32_t*)&h1);
}

// -------------------- Kernel 0b: transpose W0 -> [n][k] fp16 ----------------
__global__ void convB_kernel(const float* __restrict__ W,
                             __half* __restrict__ hi)
{
    __shared__ float tile[32][33];
    int k0 = blockIdx.x * 32;
    int n0 = blockIdx.y * 32;
    int tx = threadIdx.x, ty = threadIdx.y;   // block (32, 8)
#pragma unroll
    for (int r = 0; r < 4; r++) {
        int kk = ty + r * 8;
        int k  = k0 + kk;
        tile[kk][tx] = (k < IN_DIM) ? W[(size_t)k * HID + n0 + tx] : 0.0f;
    }
    __syncthreads();
#pragma unroll
    for (int r = 0; r < 4; r++) {
        int nn = ty + r * 8;
        hi[(size_t)(n0 + nn) * K_PAD + k0 + tx] = __float2half(tile[tx][nn]);
    }
}

// -------------------- Kernel 1: fp16 warp-MMA GEMM, pure cp.async -----------
__device__ __forceinline__ void ldg_chunk(uint32_t base, int k0, int t,
                                          const __half* Ah, const __half* Bh)
{
#pragma unroll
    for (int i = 0; i < 2; i++) {
        int lin = t + i * 512;
        int row = lin >> 3, seg = lin & 7;
        uint32_t so = sw128((uint32_t)(row * 128 + seg * 16));
        cp_async16(base + so, Ah + (size_t)row * K_PAD + k0 + seg * 8);
    }
#pragma unroll
    for (int i = 0; i < 4; i++) {
        int lin = t + i * 512;
        int row = lin >> 3, seg = lin & 7;
        uint32_t so = sw128((uint32_t)(row * 128 + seg * 16));
        cp_async16(base + A_BYTES + so, Bh + (size_t)row * K_PAD + k0 + seg * 8);
    }
}

__global__ __launch_bounds__(512, 1)
void gemm_mma_kernel(__half* __restrict__ Xout)
{
    extern __shared__ __align__(1024) char smem[];
    const uint32_t sb = smem_u32(smem);
    const int t    = threadIdx.x;
    const int wid  = t >> 5;
    const int lane = t & 31;
    const int wy   = wid >> 2;
    const int wx   = wid & 3;

    const __half* Ah = g_Ah  + (size_t)(blockIdx.y * BM) * K_PAD;
    const __half* Bh = g_Bhi + (size_t)(blockIdx.x * BN) * K_PAD;

    float acc[2][8][4];
#pragma unroll
    for (int i = 0; i < 2; i++)
#pragma unroll
        for (int j = 0; j < 8; j++)
#pragma unroll
            for (int q = 0; q < 4; q++) acc[i][j][q] = 0.0f;

    const int a_row = (lane & 15);
    const int a_k8  = (lane >> 4);
    const int b_row = ((lane >> 4) << 3) + (lane & 7);
    const int b_k8  = (lane >> 3) & 1;

#pragma unroll
    for (int s = 0; s < NSTAGE - 1; s++) {
        ldg_chunk(sb + s * STAGE, s * BK, t, Ah, Bh);
        cp_commit();
    }

    for (int c = 0; c < NCHUNK; c++) {
        asm volatile("cp.async.wait_group %0;" :: "n"(NSTAGE - 2) : "memory");
        __syncthreads();

        if (c + NSTAGE - 1 < NCHUNK)
            ldg_chunk(sb + ((c + NSTAGE - 1) % NSTAGE) * STAGE,
                      (c + NSTAGE - 1) * BK, t, Ah, Bh);
        cp_commit();

        const uint32_t base = sb + (c % NSTAGE) * STAGE;
        const uint32_t aH = base;
        const uint32_t bH = base + A_BYTES;

#pragma unroll
        for (int kk = 0; kk < 4; kk++) {
            uint32_t ah[2][4];
#pragma unroll
            for (int mt = 0; mt < 2; mt++) {
                int row = wy * 32 + mt * 16 + a_row;
                int kcol = kk * 16 + a_k8 * 8;
                uint32_t off = sw128((uint32_t)(row * 128 + kcol * 2));
                ldmx4(ah[mt], aH + off);
            }
#pragma unroll
            for (int ng = 0; ng < 4; ng++) {
                int n = wx * 64 + ng * 16 + b_row;
                int kcol = kk * 16 + b_k8 * 8;
                uint32_t off = sw128((uint32_t)(n * 128 + kcol * 2));
                uint32_t bh[4];
                ldmx4(bh, bH + off);
#pragma unroll
                for (int mt = 0; mt < 2; mt++) {
                    mma_fp16(acc[mt][2 * ng],     ah[mt], bh);
                    mma_fp16(acc[mt][2 * ng + 1], ah[mt], bh + 2);
                }
            }
        }
        __syncthreads();
    }

    __half* dst = Xout + (size_t)(blockIdx.y * BM + wy * 32) * HID
                + blockIdx.x * BN + wx * 64;
    const int r0 = lane >> 2;
    const int c0 = (lane & 3) * 2;
#pragma unroll
    for (int mt = 0; mt < 2; mt++) {
#pragma unroll
        for (int nt = 0; nt < 8; nt++) {
            __half2 h01 = __floats2half2_rn(acc[mt][nt][0], acc[mt][nt][1]);
            __half2 h23 = __floats2half2_rn(acc[mt][nt][2], acc[mt][nt][3]);
            *(__half2*)(dst + (size_t)(mt * 16 + r0) * HID + nt * 8 + c0) = h01;
            *(__half2*)(dst + (size_t)(mt * 16 + r0 + 8) * HID + nt * 8 + c0) = h23;
        }
    }
}

// -------------------- Kernel 2: f0 = X@v0, f1 = X@v1 (fp16 X) ---------------
__global__ void fvec_kernel(const __half* __restrict__ Xh,
                            const float* __restrict__ v0,
                            const float* __restrict__ v1,
                            float* __restrict__ f0, float* __restrict__ f1)
{
    int row  = blockIdx.x * 8 + (threadIdx.x >> 5);
    int lane = threadIdx.x & 31;
    const uint4* xr = (const uint4*)(Xh + (size_t)row * HID);
    const float4* w0 = (const float4*)v0;
    const float4* w1 = (const float4*)v1;
    float s0 = 0.f, s1 = 0.f;
#pragma unroll
    for (int i = 0; i < 2; i++) {
        int u = lane + i * 32;
        uint4 xv = xr[u];
        const __half2* xp = (const __half2*)&xv;
#pragma unroll
        for (int p = 0; p < 2; p++) {
            float2 e0 = __half22float2(xp[p * 2 + 0]);
            float2 e1 = __half22float2(xp[p * 2 + 1]);
            float4 a = w0[u * 2 + p];
            float4 b = w1[u * 2 + p];
            s0 += e0.x * a.x + e0.y * a.y + e1.x * a.z + e1.y * a.w;
            s1 += e0.x * b.x + e0.y * b.y + e1.x * b.z + e1.y * b.w;
        }
    }
#pragma unroll
    for (int o = 16; o > 0; o >>= 1) {
        s0 += __shfl_xor_sync(0xffffffffu, s0, o);
        s1 += __shfl_xor_sync(0xffffffffu, s1, o);
    }
    if (lane == 0) { f0[row] = s0; f1[row] = s1; }
}

// -------------------- Kernel 3: sparsify graph rows -------------------------
__global__ __launch_bounds__(512)
void sparsify_kernel(const float* __restrict__ graph,
                     int* __restrict__ idx, int* __restrict__ cnt)
{
    int row = blockIdx.x;
    __shared__ int c;
    if (threadIdx.x == 0) c = 0;
    __syncthreads();
    const float4* g = (const float4*)(graph + (size_t)row * M_N);
    const int t = threadIdx.x;
    float4 v[4];
#pragma unroll
    for (int i = 0; i < 4; i++) v[i] = __ldg(&g[t + i * 512]);
#pragma unroll
    for (int i = 0; i < 4; i++) {
        int b = (t + i * 512) * 4;
        if (v[i].x != 0.0f) { int s = atomicAdd(&c, 1); if (s < MAXD) idx[row * MAXD + s] = b + 0; }
        if (v[i].y != 0.0f) { int s = atomicAdd(&c, 1); if (s < MAXD) idx[row * MAXD + s] = b + 1; }
        if (v[i].z != 0.0f) { int s = atomicAdd(&c, 1); if (s < MAXD) idx[row * MAXD + s] = b + 2; }
        if (v[i].w != 0.0f) { int s = atomicAdd(&c, 1); if (s < MAXD) idx[row * MAXD + s] = b + 3; }
    }
    __syncthreads();
    if (threadIdx.x == 0) cnt[row] = (c < MAXD) ? c : MAXD;
}

// -------------------- Kernel 4: fused attention + agg + ELU + W1 ------------
// Softmax uses shift-invariance: no max reduction needed (scores in [-.5,.5]).
__global__ __launch_bounds__(256)
void attn_kernel(const __half* __restrict__ Xh,
                 const float* __restrict__ f0, const float* __restrict__ f1,
                 const float* __restrict__ W1,
                 const int* __restrict__ idx, const int* __restrict__ cnt,
                 float* __restrict__ out)
{
    const int row = blockIdx.x;
    const int t   = threadIdx.x;

    // NOTE: all float4-accessed shared arrays carry explicit 16B alignment
    // (R8 failed because s_inv broke the packed layout's natural alignment).
    __shared__ __align__(16) float s_hq[4 * HID];
    __shared__ __align__(16) float s_h[HID];
    __shared__ __align__(16) float s_e[MAXD];
    __shared__ __align__(16) float s_part[8][32];
    __shared__ int   s_idx[MAXD];
    __shared__ float s_inv;

    const int n = cnt[row];              // 1..MAXD (self loop guarantees >=1)

    // scores -> unnormalized softmax weights (one thread per neighbor)
    if (t < n) {
        int id = idx[row * MAXD + t];
        s_idx[t] = id;
        float e   = f0[row] + f1[id];
        float sig = 1.0f / (1.0f + __expf(-e));
        s_e[t] = __expf(sig - 0.5f);
    }
    __syncthreads();

    // sum via single warp + shuffles
    if (t < 32) {
        float s = 0.0f;
        for (int j = t; j < n; j += 32) s += s_e[j];
#pragma unroll
        for (int o = 16; o > 0; o >>= 1) s += __shfl_xor_sync(0xffffffffu, s, o);
        if (t == 0) s_inv = 1.0f / fmaxf(s, 1e-30f);
    }
    __syncthreads();
    const float inv = s_inv;

    // aggregation: quarter q handles neighbors j ≡ q (mod 4), unrolled x2
    const int q = t >> 6;
    const int u = t & 63;
    float acc[8];
#pragma unroll
    for (int i = 0; i < 8; i++) acc[i] = 0.0f;

    int j = q;
    for (; j + 4 < n; j += 8) {
        const float a0 = s_e[j] * inv;
        const float a1 = s_e[j + 4] * inv;
        const uint4 xv0 = *((const uint4*)(Xh + (size_t)s_idx[j] * HID) + u);
        const uint4 xv1 = *((const uint4*)(Xh + (size_t)s_idx[j + 4] * HID) + u);
        const __half2* p0 = (const __half2*)&xv0;
        const __half2* p1 = (const __half2*)&xv1;
#pragma unroll
        for (int p = 0; p < 4; p++) {
            float2 fa = __half22float2(p0[p]);
            float2 fb = __half22float2(p1[p]);
            acc[2 * p]     += a0 * fa.x + a1 * fb.x;
            acc[2 * p + 1] += a0 * fa.y + a1 * fb.y;
        }
    }
    if (j < n) {
        const float a0 = s_e[j] * inv;
        const uint4 xv0 = *((const uint4*)(Xh + (size_t)s_idx[j] * HID) + u);
        const __half2* p0 = (const __half2*)&xv0;
#pragma unroll
        for (int p = 0; p < 4; p++) {
            float2 fa = __half22float2(p0[p]);
            acc[2 * p]     += a0 * fa.x;
            acc[2 * p + 1] += a0 * fa.y;
        }
    }
    ((float4*)(s_hq + q * HID))[u * 2] =
        make_float4(acc[0], acc[1], acc[2], acc[3]);
    ((float4*)(s_hq + q * HID))[u * 2 + 1] =
        make_float4(acc[4], acc[5], acc[6], acc[7]);
    __syncthreads();

    if (t < 128) {
        float4 r = make_float4(0.f, 0.f, 0.f, 0.f);
#pragma unroll
        for (int qq = 0; qq < 4; qq++) {
            float4 v = ((const float4*)s_hq)[qq * 128 + t];
            r.x += v.x; r.y += v.y; r.z += v.z; r.w += v.w;
        }
        r.x = (r.x > 0.f) ? r.x : expm1f(r.x);
        r.y = (r.y > 0.f) ? r.y : expm1f(r.y);
        r.z = (r.z > 0.f) ? r.z : expm1f(r.z);
        r.w = (r.w > 0.f) ? r.w : expm1f(r.w);
        ((float4*)s_h)[t] = r;
    }
    __syncthreads();

    if (t < 240) {
        int k  = t % 30;
        int sl = t / 30;
        float p = 0.0f;
        const int d0 = sl * 64;
#pragma unroll 8
        for (int d = d0; d < d0 + 64; d++) p += s_h[d] * W1[d * LAT + k];
        s_part[sl][k] = p;
    }
    __syncthreads();
    if (t < LAT) {
        float r = 0.0f;
#pragma unroll
        for (int sl = 0; sl < 8; sl++) r += s_part[sl][t];
        out[(size_t)row * LAT + t] = r;
    }
}

// -------------------- launch -------------------------------------------------
extern "C" void kernel_launch(void* const* d_in, const int* in_sizes, int n_in,
                              void* d_out, int out_size)
{
    const float* node_features = (const float*)d_in[0]; // [8192,3000]
    const float* graph         = (const float*)d_in[1]; // [8192,8192]
    const float* W0            = (const float*)d_in[2]; // [3000,512]
    const float* v0            = (const float*)d_in[3]; // [512]
    const float* v1            = (const float*)d_in[4]; // [512]
    const float* W1            = (const float*)d_in[5]; // [512,30]
    float* out = (float*)d_out;

    __half *Ah, *Xh, *Bhi;
    float *f0, *f1;
    int *idx, *cnt;
    cudaGetSymbolAddress((void**)&Ah,  g_Ah);
    cudaGetSymbolAddress((void**)&Xh,  g_Xh);
    cudaGetSymbolAddress((void**)&f0,  g_f0);
    cudaGetSymbolAddress((void**)&f1,  g_f1);
    cudaGetSymbolAddress((void**)&idx, g_idx);
    cudaGetSymbolAddress((void**)&cnt, g_cnt);
    cudaGetSymbolAddress((void**)&Bhi, g_Bhi);

    static cudaStream_t s2 = nullptr;
    static cudaEvent_t evFork = nullptr, evB = nullptr, evJoin = nullptr;
    if (s2 == nullptr) {
        cudaStreamCreateWithFlags(&s2, cudaStreamNonBlocking);
        cudaEventCreateWithFlags(&evFork, cudaEventDisableTiming);
        cudaEventCreateWithFlags(&evB,    cudaEventDisableTiming);
        cudaEventCreateWithFlags(&evJoin, cudaEventDisableTiming);
        cudaFuncSetAttribute(gemm_mma_kernel,
                             cudaFuncAttributeMaxDynamicSharedMemorySize,
                             SMEM_TOTAL);
    }

    // fork: convB then sparsify run on s2 concurrently with convA
    cudaEventRecord(evFork, 0);
    cudaStreamWaitEvent(s2, evFork, 0);
    convB_kernel<<<dim3(K_PAD / 32, HID / 32), dim3(32, 8), 0, s2>>>(W0, Bhi);
    cudaEventRecord(evB, s2);
    sparsify_kernel<<<M_N, 512, 0, s2>>>(graph, idx, cnt);
    cudaEventRecord(evJoin, s2);

    // main chain
    convA_kernel<<<dim3(3, M_N), 256>>>(node_features, Ah);
    cudaStreamWaitEvent(0, evB, 0);
    gemm_mma_kernel<<<dim3(HID / BN, M_N / BM), 512, SMEM_TOTAL>>>(Xh);
    fvec_kernel<<<M_N / 8, 256>>>(Xh, v0, v1, f0, f1);

    // join: attn needs both the GEMM chain and sparsify
    cudaStreamWaitEvent(0, evJoin, 0);
    attn_kernel<<<M_N, 256>>>(Xh, f0, f1, W1, idx, cnt, out);
}